// round 1
// baseline (speedup 1.0000x reference)
#include <cuda_runtime.h>
#include <cuda_bf16.h>

// ES-RNN (Holt-Winters) forward scan.
// Inputs (metadata order): y[N,512] f32, idxs[N] i32, lev_sms[M,1] f32,
// seas_sms[M,1] f32 (UNUSED by reference!), init_seas[M,24] f32, (+ scalar ints).
// Output (flattened tuple): levels[N,512] | seasonalities[N,536] | logd[N,511], f32.

#define ES_NTIME 512
#define ES_SEAS  24
#define ES_SEASW 536   // 24 init + 1 init0 + 511 seasons
#define ES_LOGW  511

// One smoothing step. POS is a compile-time constant -> S[] stays in registers.
#define ES_STEP(POS, YT, LV, SV) do {                               \
    float _seas = S[POS];                                           \
    float _r1   = __fdividef((YT), _seas);                          \
    float _nl   = fmaf(a, _r1 - lev, lev);                          \
    float _ns   = fmaf(a, __fdividef((YT), _nl) - _seas, _seas);    \
    float _nlg  = __logf(_nl);                                      \
    *logd_out++ = _nlg - loglev;                                    \
    loglev = _nlg; lev = _nl; S[POS] = _ns;                         \
    (LV) = _nl; (SV) = _ns;                                         \
} while (0)

// Four steps + one float4 store each for levels and seasonalities.
#define ES_GROUP4(P0, P1, P2, P3) do {                              \
    float4 _yv = *y4++;                                             \
    float4 _lo, _so;                                                \
    ES_STEP(P0, _yv.x, _lo.x, _so.x);                               \
    ES_STEP(P1, _yv.y, _lo.y, _so.y);                               \
    ES_STEP(P2, _yv.z, _lo.z, _so.z);                               \
    ES_STEP(P3, _yv.w, _lo.w, _so.w);                               \
    *lev4++ = _lo; *sea4++ = _so;                                   \
} while (0)

__global__ __launch_bounds__(64)
void ES_51994874085958_kernel(
    const float* __restrict__ y,
    const int*   __restrict__ idxs,
    const float* __restrict__ lev_sms_p,
    const float* __restrict__ init_seas_p,
    float*       __restrict__ out,
    int n_series)
{
    int s = blockIdx.x * blockDim.x + threadIdx.x;
    if (s >= n_series) return;

    const int idx = idxs[s];
    // NOTE: reference uses lev_sms for BOTH coefficients (seas_sms input unused).
    const float a = 1.0f / (1.0f + __expf(-lev_sms_p[idx]));

    // Seasonal state in registers, loaded via aligned float4 (idx*24 floats = idx*96 B, 16B-aligned).
    float S[ES_SEAS];
    {
        const float4* is4 = (const float4*)(init_seas_p + (size_t)idx * ES_SEAS);
        #pragma unroll
        for (int k = 0; k < 6; ++k) {
            float4 v = is4[k];
            S[4 * k + 0] = __expf(v.x);
            S[4 * k + 1] = __expf(v.y);
            S[4 * k + 2] = __expf(v.z);
            S[4 * k + 3] = __expf(v.w);
        }
    }

    float* lev_out  = out + (size_t)s * ES_NTIME;
    float* seas_out = out + (size_t)n_series * ES_NTIME + (size_t)s * ES_SEASW;
    float* logd_out = out + (size_t)n_series * (ES_NTIME + ES_SEASW) + (size_t)s * ES_LOGW;

    // seasonalities[0..23] = exp(init_seas)
    {
        float4* so4 = (float4*)seas_out;
        #pragma unroll
        for (int k = 0; k < 6; ++k)
            so4[k] = make_float4(S[4 * k], S[4 * k + 1], S[4 * k + 2], S[4 * k + 3]);
    }

    const float4* y4   = (const float4*)(y + (size_t)s * ES_NTIME);
    float4*       lev4 = (float4*)lev_out;
    float4*       sea4 = (float4*)(seas_out + ES_SEAS);   // offset 24 floats -> 16B aligned

    float lev, loglev;

    // ---- Prologue: t = 0..3 (group 0: [lev0, L1, L2, L3], [init0, s1, s2, s3]) ----
    {
        float4 yv = *y4++;
        lev    = __fdividef(yv.x, S[0]);
        loglev = __logf(lev);
        float4 lo, so;
        lo.x = lev;
        so.x = S[0];
        ES_STEP(1, yv.y, lo.y, so.y);
        ES_STEP(2, yv.z, lo.z, so.z);
        ES_STEP(3, yv.w, lo.w, so.w);
        *lev4++ = lo;
        *sea4++ = so;
    }

    // ---- Main: t = 4..507, 21 chunks of one full seasonal period (24 steps) ----
    #pragma unroll 1
    for (int c = 0; c < 21; ++c) {
        ES_GROUP4( 4,  5,  6,  7);
        ES_GROUP4( 8,  9, 10, 11);
        ES_GROUP4(12, 13, 14, 15);
        ES_GROUP4(16, 17, 18, 19);
        ES_GROUP4(20, 21, 22, 23);
        ES_GROUP4( 0,  1,  2,  3);
    }

    // ---- Epilogue: t = 508..511 (508 % 24 == 4) ----
    ES_GROUP4(4, 5, 6, 7);
}

extern "C" void kernel_launch(void* const* d_in, const int* in_sizes, int n_in,
                              void* d_out, int out_size)
{
    const float* y         = (const float*)d_in[0];
    const int*   idxs      = (const int*)d_in[1];
    const float* lev_sms   = (const float*)d_in[2];
    // d_in[3] = seas_sms: unused by the reference (it re-uses lev_sms).
    const float* init_seas = (const float*)d_in[4];

    int n_series = in_sizes[0] / ES_NTIME;

    int threads = 64;
    int blocks  = (n_series + threads - 1) / threads;
    ES_51994874085958_kernel<<<blocks, threads>>>(
        y, idxs, lev_sms, init_seas, (float*)d_out, n_series);
}

// round 2
// speedup vs baseline: 2.1330x; 2.1330x over previous
#include <cuda_runtime.h>
#include <cuda_bf16.h>

// ES-RNN (Holt-Winters) forward scan, smem-transpose staged for coalescing.
// Output (flattened): levels[N,512] | seasonalities[N,536] | logd[N,511], f32.

#define TPB    128
#define T      16          // timesteps per tile
#define NT     32          // 512 / 16
#define YSTR   17          // smem row stride (odd -> conflict-free)
#define NTIME  512
#define SEASW  536
#define LOGW   511

// ---- cooperative, coalesced y tile load into registers ----
__device__ __forceinline__ void load_tile(const float* __restrict__ y, int sbase,
                                          int n_series, int tile, float4 (&pf)[4]) {
#pragma unroll
    for (int k = 0; k < 4; ++k) {
        int l   = threadIdx.x + TPB * k;   // 0..511
        int row = l >> 2, c4 = l & 3;      // 4 float4 per 16-col row
        int sr  = sbase + row;
        if (sr < n_series)
            pf[k] = *(const float4*)(y + (size_t)sr * NTIME + tile * T + 4 * c4);
        else
            pf[k] = make_float4(1.f, 1.f, 1.f, 1.f);
    }
}

__device__ __forceinline__ void sts_tile(float* buf, const float4 (&pf)[4]) {
#pragma unroll
    for (int k = 0; k < 4; ++k) {
        int l   = threadIdx.x + TPB * k;
        int row = l >> 2, c4 = l & 3;
        float* p = buf + row * YSTR + 4 * c4;
        p[0] = pf[k].x; p[1] = pf[k].y; p[2] = pf[k].z; p[3] = pf[k].w;
    }
}

// ---- coalesced float4 flush (lev / seas streams, 16B-aligned rows) ----
__device__ __forceinline__ void flush_f4(const float* buf, float* gbase,
                                         int rowstride, int coloff,
                                         int sbase, int n_series) {
#pragma unroll
    for (int k = 0; k < 4; ++k) {
        int l   = threadIdx.x + TPB * k;
        int row = l >> 2, c4 = l & 3;
        const float* p = buf + row * YSTR + 4 * c4;
        float4 v = make_float4(p[0], p[1], p[2], p[3]);
        int sr = sbase + row;
        if (sr < n_series)
            *(float4*)(gbase + (size_t)sr * rowstride + coloff + 4 * c4) = v;
    }
}

// ---- coalesced scalar flush for logd (row stride 511: only 4B-aligned) ----
__device__ __forceinline__ void flush_logd(const float* buf, float* gbase,
                                           int tile, int sbase, int n_series) {
#pragma unroll
    for (int k = 0; k < 16; ++k) {
        int l   = threadIdx.x + TPB * k;
        int row = l >> 4, col = l & 15;
        int g   = tile * T + col - 1;      // logd[t] stored at t-1; t=0 skipped
        int sr  = sbase + row;
        if (g >= 0 && sr < n_series)
            gbase[(size_t)sr * LOGW + g] = buf[row * YSTR + col];
    }
}

// ---- 16 recurrence steps; PHASE = (16*tile) % 24, compile-time ----
template<int PHASE, bool FIRST>
__device__ __forceinline__ void compute_tile(
    const float* yrow, float* lrow, float* srow, float* drow,
    float (&S)[24], float& lev, float& loglev, float a)
{
#pragma unroll
    for (int j = 0; j < T; ++j) {
        float yt = yrow[j];
        if (FIRST && j == 0) {
            lev    = __fdividef(yt, S[0]);
            loglev = __logf(lev);
            lrow[0] = lev;
            srow[0] = S[0];     // seasonalities[24] = init_seas[:,0]
            drow[0] = 0.0f;     // unused slot (not flushed)
        } else {
            const int pos = (PHASE + j) % 24;   // compile-time
            float seas = S[pos];
            float nl = fmaf(a, __fdividef(yt, seas) - lev, lev);
            float ns = fmaf(a, __fdividef(yt, nl) - seas, seas);
            float nlg = __logf(nl);
            drow[j] = nlg - loglev;
            lrow[j] = nl;
            srow[j] = ns;
            lev = nl; loglev = nlg; S[pos] = ns;
        }
    }
}

__global__ __launch_bounds__(TPB)
void ES_51994874085958_kernel(
    const float* __restrict__ y,
    const int*   __restrict__ idxs,
    const float* __restrict__ lev_sms_p,
    const float* __restrict__ init_seas_p,
    float*       __restrict__ out,
    int n_series)
{
    __shared__ float shY[2][TPB * YSTR];
    __shared__ float shLev[TPB * YSTR];
    __shared__ float shSeas[TPB * YSTR];
    __shared__ float shLogd[TPB * YSTR];

    const int tid   = threadIdx.x;
    const int sbase = blockIdx.x * TPB;
    const int s     = sbase + tid;
    const bool valid = (s < n_series);

    float* out_lev  = out;
    float* out_seas = out + (size_t)n_series * NTIME;
    float* out_logd = out + (size_t)n_series * (NTIME + SEASW);

    // per-series params + seasonal state in registers
    float a = 0.5f;
    float S[24];
    if (valid) {
        const int idx = idxs[s];
        // reference uses lev_sms for BOTH smoothing coefficients
        a = 1.0f / (1.0f + __expf(-lev_sms_p[idx]));
        const float4* is4 = (const float4*)(init_seas_p + (size_t)idx * 24);
#pragma unroll
        for (int k = 0; k < 6; ++k) {
            float4 v = is4[k];
            S[4 * k + 0] = __expf(v.x);
            S[4 * k + 1] = __expf(v.y);
            S[4 * k + 2] = __expf(v.z);
            S[4 * k + 3] = __expf(v.w);
        }
        // seasonalities[0..23] = exp(init_seas)  (once, small divergent write)
        float4* so4 = (float4*)(out_seas + (size_t)s * SEASW);
#pragma unroll
        for (int k = 0; k < 6; ++k)
            so4[k] = make_float4(S[4 * k], S[4 * k + 1], S[4 * k + 2], S[4 * k + 3]);
    } else {
#pragma unroll
        for (int k = 0; k < 24; ++k) S[k] = 1.0f;
    }

    float lev = 1.0f, loglev = 0.0f;
    float4 pf[4];

    // prime tile 0
    load_tile(y, sbase, n_series, 0, pf);
    sts_tile(shY[0], pf);
    __syncthreads();

    int cur = 0;
    const float* yrow;
    float* lrow = shLev  + tid * YSTR;
    float* srow = shSeas + tid * YSTR;
    float* drow = shLogd + tid * YSTR;

#define DO_TILE(TI, PHASE, FIRST, HAS_NEXT) do {                                  \
        if (HAS_NEXT) load_tile(y, sbase, n_series, (TI) + 1, pf);                \
        yrow = shY[cur] + tid * YSTR;                                             \
        compute_tile<PHASE, FIRST>(yrow, lrow, srow, drow, S, lev, loglev, a);    \
        if (HAS_NEXT) sts_tile(shY[cur ^ 1], pf);                                 \
        __syncthreads();                                                          \
        flush_f4(shLev,  out_lev,  NTIME, (TI) * T,      sbase, n_series);        \
        flush_f4(shSeas, out_seas, SEASW, 24 + (TI) * T, sbase, n_series);        \
        flush_logd(shLogd, out_logd, (TI), sbase, n_series);                      \
        __syncthreads();                                                          \
        cur ^= 1;                                                                 \
    } while (0)

    // tile 0 (phase 0, contains the t=0 special step)
    DO_TILE(0, 0, true, true);

    // tiles 1..30: phases repeat {16, 8, 0}
    int i = 1;
#pragma unroll 1
    for (int g = 0; g < 10; ++g) {
        DO_TILE(i, 16, false, true); ++i;
        DO_TILE(i,  8, false, true); ++i;
        DO_TILE(i,  0, false, true); ++i;
    }

    // tile 31 (phase (16*31)%24 = 16), no prefetch
    DO_TILE(31, 16, false, false);

#undef DO_TILE
}

extern "C" void kernel_launch(void* const* d_in, const int* in_sizes, int n_in,
                              void* d_out, int out_size)
{
    const float* y         = (const float*)d_in[0];
    const int*   idxs      = (const int*)d_in[1];
    const float* lev_sms   = (const float*)d_in[2];
    // d_in[3] = seas_sms: unused by the reference (it re-uses lev_sms).
    const float* init_seas = (const float*)d_in[4];

    int n_series = in_sizes[0] / NTIME;
    int blocks   = (n_series + TPB - 1) / TPB;

    ES_51994874085958_kernel<<<blocks, TPB>>>(
        y, idxs, lev_sms, init_seas, (float*)d_out, n_series);
}

// round 9
// speedup vs baseline: 2.6068x; 1.2221x over previous
#include <cuda_runtime.h>
#include <cuda_bf16.h>

// ES-RNN (Holt-Winters) forward scan, warp-specialized producer/consumer.
// Block = 64 threads: warp0 computes 32 series (smem-only), warp1 does all
// global I/O (prefetch y, flush outputs), double-buffered.
// Output (flattened): levels[N,512] | seasonalities[N,536] | logd[N,511], f32.

#define NTIME 512
#define SEASW 536
#define LOGW  511
#define STR   17      // smem row stride (odd -> conflict-free scalar access)

// ---------------- IO-warp helpers (32 lanes) ----------------

__device__ __forceinline__ void io_load(const float* __restrict__ y, int sbase,
                                        int n, int tile, int lane, float4 (&pf)[4]) {
#pragma unroll
    for (int k = 0; k < 4; ++k) {
        int l = lane + 32 * k;          // 0..127 -> 128 float4 = 32 rows x 16 cols
        int row = l >> 2, c4 = l & 3;
        int sr = sbase + row;
        pf[k] = (sr < n) ? *(const float4*)(y + (size_t)sr * NTIME + tile * 16 + 4 * c4)
                         : make_float4(1.f, 1.f, 1.f, 1.f);
    }
}

__device__ __forceinline__ void io_sts(float* buf, int lane, const float4 (&pf)[4]) {
#pragma unroll
    for (int k = 0; k < 4; ++k) {
        int l = lane + 32 * k;
        int row = l >> 2, c4 = l & 3;
        float* p = buf + row * STR + 4 * c4;
        p[0] = pf[k].x; p[1] = pf[k].y; p[2] = pf[k].z; p[3] = pf[k].w;
    }
}

__device__ __forceinline__ void io_flush_f4(const float* buf, float* g, int rowstride,
                                            int coloff, int sbase, int n, int lane) {
#pragma unroll
    for (int k = 0; k < 4; ++k) {
        int l = lane + 32 * k;
        int row = l >> 2, c4 = l & 3;
        const float* p = buf + row * STR + 4 * c4;
        float4 v = make_float4(p[0], p[1], p[2], p[3]);
        int sr = sbase + row;
        if (sr < n) *(float4*)(g + (size_t)sr * rowstride + coloff + 4 * c4) = v;
    }
}

__device__ __forceinline__ void io_flush_logd(const float* buf, float* g, int tile,
                                              int sbase, int n, int lane) {
#pragma unroll
    for (int k = 0; k < 16; ++k) {
        int l = lane + 32 * k;          // 512 values = 32 rows x 16 cols
        int row = l >> 4, col = l & 15;
        int gcol = tile * 16 + col - 1; // logd[t] lives at t-1; t=0 skipped
        int sr = sbase + row;
        if (gcol >= 0 && sr < n) g[(size_t)sr * LOGW + gcol] = buf[row * STR + col];
    }
}

// ---------------- compute warp: 16 steps, PHASE = (16*tile)%24 ----------------

template<int PHASE, bool FIRST>
__device__ __forceinline__ void compute_tile(
    const float* yrow, float* lrow, float* srow, float* drow,
    float (&S)[24], float& lev, float& loglev, float a)
{
    float yv[16], q[16];
#pragma unroll
    for (int j = 0; j < 16; ++j) yv[j] = yrow[j];
    // positions within a tile are distinct (16 < 24) -> all divisions use
    // pre-tile seasonal state: 16 independent MUFU RCPs, fully pipelined.
#pragma unroll
    for (int j = 0; j < 16; ++j) q[j] = __fdividef(yv[j], S[(PHASE + j) % 24]);
#pragma unroll
    for (int j = 0; j < 16; ++j) {
        if (FIRST && j == 0) {
            lev = q[0];                  // lev0 = y0 / init_seas0
            loglev = __logf(lev);
            lrow[0] = lev;
            srow[0] = S[0];              // seasonalities[24] = init_seas[:,0]
        } else {
            const int pos = (PHASE + j) % 24;
            float seas = S[pos];
            float nl  = fmaf(a, q[j] - lev, lev);
            float ns  = fmaf(a, __fdividef(yv[j], nl) - seas, seas);
            float nlg = __logf(nl);
            drow[j] = nlg - loglev;
            lrow[j] = nl;
            srow[j] = ns;
            lev = nl; loglev = nlg; S[pos] = ns;
        }
    }
}

__global__ __launch_bounds__(64)
void ES_51994874085958_kernel(
    const float* __restrict__ y,
    const int*   __restrict__ idxs,
    const float* __restrict__ lev_sms_p,
    const float* __restrict__ init_seas_p,
    float*       __restrict__ out,
    int n_series)
{
    __shared__ float shY[2][32 * STR];
    __shared__ float shLev[2][32 * STR];
    __shared__ float shSeas[2][32 * STR];
    __shared__ float shLogd[2][32 * STR];
    __shared__ float shInit[32 * 25];    // 32 series x 24 init seasonals (stride 25)

    const int tid  = threadIdx.x;
    const int lane = tid & 31;
    const bool is_compute = (tid < 32);
    const int sbase = blockIdx.x * 32;

    float* out_lev  = out;
    float* out_seas = out + (size_t)n_series * NTIME;
    float* out_logd = out + (size_t)n_series * (NTIME + SEASW);

    float a = 0.5f, lev = 1.0f, loglev = 0.0f;
    float S[24];
    float4 pf[4];

    if (is_compute) {
        int s = sbase + lane;
        if (s < n_series) {
            int idx = idxs[s];
            // reference uses lev_sms for BOTH smoothing coefficients
            a = 1.0f / (1.0f + __expf(-lev_sms_p[idx]));
            const float4* is4 = (const float4*)(init_seas_p + (size_t)idx * 24);
#pragma unroll
            for (int k = 0; k < 6; ++k) {
                float4 v = is4[k];
                S[4 * k + 0] = __expf(v.x);
                S[4 * k + 1] = __expf(v.y);
                S[4 * k + 2] = __expf(v.z);
                S[4 * k + 3] = __expf(v.w);
            }
        } else {
#pragma unroll
            for (int k = 0; k < 24; ++k) S[k] = 1.0f;
        }
#pragma unroll
        for (int k = 0; k < 24; ++k) shInit[lane * 25 + k] = S[k];
    } else {
        io_load(y, sbase, n_series, 0, lane, pf);
        io_sts(shY[0], lane, pf);
    }
    __syncthreads();

    // Tile i: compute reads shY[i&1], writes out-bufs[i&1].
    // IO: prefetch y tile i+1 into shY[(i+1)&1]; flush out-bufs[(i-1)&1] of tile i-1.
#define ITER(I, PHASE, FIRST, B) do {                                              \
        if (is_compute) {                                                          \
            compute_tile<PHASE, FIRST>(shY[B] + lane * STR, shLev[B] + lane * STR, \
                                       shSeas[B] + lane * STR, shLogd[B] + lane * STR, \
                                       S, lev, loglev, a);                         \
        } else {                                                                   \
            if ((I) + 1 < 32) io_load(y, sbase, n_series, (I) + 1, lane, pf);      \
            if (FIRST) {                                                           \
                /* seasonalities[:, 0:24] = exp(init_seas), coalesced */           \
                for (int r = 0; r < 32; ++r) {                                     \
                    int sr = sbase + r;                                            \
                    if (lane < 24 && sr < n_series)                                \
                        out_seas[(size_t)sr * SEASW + lane] = shInit[r * 25 + lane];\
                }                                                                  \
            } else {                                                               \
                io_flush_f4(shLev[1 - (B)],  out_lev,  NTIME, ((I) - 1) * 16,      \
                            sbase, n_series, lane);                                \
                io_flush_f4(shSeas[1 - (B)], out_seas, SEASW, 24 + ((I) - 1) * 16, \
                            sbase, n_series, lane);                                \
                io_flush_logd(shLogd[1 - (B)], out_logd, (I) - 1,                  \
                              sbase, n_series, lane);                              \
            }                                                                      \
            if ((I) + 1 < 32) io_sts(shY[((I) + 1) & 1], lane, pf);                \
        }                                                                          \
        __syncthreads();                                                           \
    } while (0)

    ITER(0, 0, true, 0);

    int i = 1;
#pragma unroll 1
    for (int g = 0; g < 5; ++g) {       // tiles 1..30, period-6 (phase x parity)
        ITER(i, 16, false, 1); ++i;
        ITER(i,  8, false, 0); ++i;
        ITER(i,  0, false, 1); ++i;
        ITER(i, 16, false, 0); ++i;
        ITER(i,  8, false, 1); ++i;
        ITER(i,  0, false, 0); ++i;
    }

    ITER(31, 16, false, 1);

    // drain: flush tile 31 (bufs parity 1)
    if (!is_compute) {
        io_flush_f4(shLev[1],  out_lev,  NTIME, 31 * 16,      sbase, n_series, lane);
        io_flush_f4(shSeas[1], out_seas, SEASW, 24 + 31 * 16, sbase, n_series, lane);
        io_flush_logd(shLogd[1], out_logd, 31, sbase, n_series, lane);
    }
#undef ITER
}

extern "C" void kernel_launch(void* const* d_in, const int* in_sizes, int n_in,
                              void* d_out, int out_size)
{
    const float* y         = (const float*)d_in[0];
    const int*   idxs      = (const int*)d_in[1];
    const float* lev_sms   = (const float*)d_in[2];
    // d_in[3] = seas_sms: unused by the reference (it re-uses lev_sms).
    const float* init_seas = (const float*)d_in[4];

    int n_series = in_sizes[0] / NTIME;
    int blocks   = (n_series + 31) / 32;

    ES_51994874085958_kernel<<<blocks, 64>>>(
        y, idxs, lev_sms, init_seas, (float*)d_out, n_series);
}